// round 14
// baseline (speedup 1.0000x reference)
#include <cuda_runtime.h>
#include <cuda_fp16.h>
#include <math.h>
#include <stdint.h>

// ---------------------------------------------------------------------------
// SpaceTimeLocalSelfAttention — R14: R13 + gather folded into the epilogue
//   (ping-pong fp16 window buffers; one-time x prep; 7 launches total).
// B=4, T=8, H=W=32, C=512, NH=8, DM=64, KT=4, KS=8
// ---------------------------------------------------------------------------

#define NWIN   64
#define SEQ    256
#define CH     512
#define NH     8
#define DM     64
#define JC     192

// attention smem (32-bit words) — R13 proven layouts
#define PQP    36
#define KHP    36
#define VTP    132
#define PQ_W   (SEQ * PQP)
#define KH_BASE PQ_W
#define KH_W   (SEQ * KHP)
#define VT_BASE (KH_BASE + KH_W)
#define VT_W   (DM * VTP)

// GEMM staging overlays (3 stages, R11/R13)
#define ASTG_W (SEQ * 20)
#define BSTG_W (JC * 20)
#define BSTG_BASE (3 * ASTG_W)
#define FUSED_SMEM ((BSTG_BASE + 3 * BSTG_W) * 4)

__device__ __half2 g_xf [NWIN * 512 * (CH / 2)];   // [n][f*64+rr][c] raw x, all 8 frames
__device__ __half2 g_xha[NWIN * 192 * (CH / 2)];   // ping-pong attended-window buffers
__device__ __half2 g_xhb[NWIN * 192 * (CH / 2)];
__device__ __half2 g_wh [NH * JC * (CH / 2)];      // [h][j][k2]

__device__ __forceinline__ uint32_t smem_u32(const void* p) {
    uint32_t a;
    asm("{ .reg .u64 t; cvta.to.shared.u64 t, %1; cvt.u32.u64 %0, t; }"
        : "=r"(a) : "l"(p));
    return a;
}
__device__ __forceinline__ void cp_async16(uint32_t dst, const void* src) {
    asm volatile("cp.async.cg.shared.global [%0], [%1], 16;"
                 :: "r"(dst), "l"(src) : "memory");
}
__device__ __forceinline__ void ldmatrix_x4(uint32_t& r0, uint32_t& r1,
                                            uint32_t& r2, uint32_t& r3, uint32_t addr)
{
    asm volatile("ldmatrix.sync.aligned.m8n8.x4.shared.b16 {%0,%1,%2,%3}, [%4];"
                 : "=r"(r0), "=r"(r1), "=r"(r2), "=r"(r3) : "r"(addr));
}
__device__ __forceinline__ void mma_f16(float& c0, float& c1, float& c2, float& c3,
                                        uint32_t a0, uint32_t a1, uint32_t a2, uint32_t a3,
                                        uint32_t b0, uint32_t b1)
{
    asm volatile(
        "mma.sync.aligned.m16n8k16.row.col.f32.f16.f16.f32 "
        "{%0,%1,%2,%3}, {%4,%5,%6,%7}, {%8,%9}, {%0,%1,%2,%3};"
        : "+f"(c0), "+f"(c1), "+f"(c2), "+f"(c3)
        : "r"(a0), "r"(a1), "r"(a2), "r"(a3), "r"(b0), "r"(b1));
}
__device__ __forceinline__ uint32_t pack_h2(float x, float y) {
    __half2 h = __float22half2_rn(make_float2(x, y));
    return *(uint32_t*)&h;
}

// ---------------------------------------------------------------------------
__global__ void wtrans_kernel(const float* __restrict__ Wq,
                              const float* __restrict__ Wk,
                              const float* __restrict__ Wv)
{
    int idx = blockIdx.x * blockDim.x + threadIdx.x;
    if (idx >= NH * JC * (CH / 2)) return;
    int k2 = idx & 255;
    int j  = (idx >> 8) % JC;
    int h  = idx / (JC * 256);
    int w  = j >> 6;
    int dm = j & 63;
    const float* W = (w == 0) ? Wq : (w == 1) ? Wk : Wv;
    float v0 = W[((size_t)h * CH + 2 * k2)     * DM + dm];
    float v1 = W[((size_t)h * CH + 2 * k2 + 1) * DM + dm];
    g_wh[idx] = __float22half2_rn(make_float2(v0, v1));
}

// ---------------------------------------------------------------------------
// One-time: x (all 8 frames) -> fp16 window layout g_xf[n][f*64+rr][c]
// ---------------------------------------------------------------------------
__global__ void xprep_kernel(const float* __restrict__ x)
{
    int idx = blockIdx.x * blockDim.x + threadIdx.x;
    if (idx >= (NWIN * 512 * CH) / 4) return;
    int e = idx * 4;
    int c = e & (CH - 1);
    int r = (e >> 9) & 511;           // f*64 + rr
    int n = e >> 18;
    int f  = r >> 6;
    int ry = (r >> 3) & 7;
    int rx = r & 7;
    int b  = n >> 4;
    int by = (n >> 2) & 3;
    int bx = n & 3;
    const float* src = x + (((((size_t)b * 8 + f) * 32 + by * 8 + ry) * 32
                             + bx * 8 + rx) * CH + c);
    float4 v = *(const float4*)src;
    g_xf[e / 2]     = __float22half2_rn(make_float2(v.x, v.y));
    g_xf[e / 2 + 1] = __float22half2_rn(make_float2(v.z, v.w));
}

// ---------------------------------------------------------------------------
__global__ __launch_bounds__(512, 1) void fused_kernel(
    float* __restrict__ outbuf, const float* __restrict__ xin, int pass,
    const float* __restrict__ bq, const float* __restrict__ bk,
    const float* __restrict__ bv)
{
    const int n = blockIdx.x >> 3;
    const int h = blockIdx.x & 7;

    extern __shared__ __align__(16) uint32_t sm[];
    uint32_t* Pq  = sm;
    uint32_t* Kh  = sm + KH_BASE;
    __half*   Vth = (__half*)(sm + VT_BASE);

    __shared__ float bias_sm[JC];

    const int tid = threadIdx.x;
    const int lane = tid & 31;
    const int gid = lane >> 2;
    const int tig = lane & 3;
    const int wid = tid >> 5;
    const int wq = wid * 16;

    if (tid < JC) {
        int dm = tid & 63;
        int wsel = tid >> 6;
        const float* bb = (wsel == 0) ? bq : (wsel == 1) ? bk : bv;
        bias_sm[tid] = bb[h * DM + dm];
    }

    // A-tile sources: rows 0..191 attended (ping-pong) or g_xf (pass 0);
    // rows 192..255 raw frame pass+3 from g_xf.
    __half2* xw = (pass & 1) ? g_xha : g_xhb;            // written for pass+1
    const __half2* xr = (pass & 1) ? g_xhb : g_xha;      // written by pass-1
    const __half2* Alo = (pass == 0)
        ? g_xf + (size_t)n * 512 * (CH / 2)
        : xr   + (size_t)n * 192 * (CH / 2);
    const __half2* Ahi = g_xf + ((size_t)n * 512 + (pass + 3) * 64 - 192) * (CH / 2);
    const __half2* Bbase = g_wh + (size_t)h * JC * (CH / 2);

    const uint32_t smem_base = smem_u32(sm);
    const uint32_t a_off = (((wq + (lane & 15)) * 40) + ((lane >> 4) << 3)) * 2;
    const uint32_t b_off = ((((lane & 7) + ((lane >> 4) << 3)) * 40) +
                            (((lane >> 3) & 1) << 3)) * 2;

    float c[24][4];
#pragma unroll
    for (int nt = 0; nt < 24; nt++)
#pragma unroll
        for (int r = 0; r < 4; r++) c[nt][r] = 0.f;

#define STAGE_LOAD(st, kc2)                                                     \
    {                                                                           \
        uint32_t ab = smem_base + (st) * (ASTG_W * 4);                          \
        _Pragma("unroll")                                                       \
        for (int i = 0; i < 2; i++) {                                           \
            int ck = tid + 512 * i;                                             \
            int row = ck >> 2, cg = ck & 3;                                     \
            const __half2* asrc = (row < 192 ? Alo : Ahi);                      \
            cp_async16(ab + (row * 20 + cg * 4) * 4,                            \
                       asrc + (size_t)row * (CH / 2) + (kc2) + cg * 4);         \
        }                                                                       \
        uint32_t bb2 = smem_base + (BSTG_BASE + (st) * BSTG_W) * 4;             \
        for (int ck = tid; ck < 768; ck += 512) {                               \
            int j = ck >> 2, cg = ck & 3;                                       \
            cp_async16(bb2 + (j * 20 + cg * 4) * 4,                             \
                       Bbase + (size_t)j * (CH / 2) + (kc2) + cg * 4);          \
        }                                                                       \
    }

    // ---- Phase 1: GEMM (R11/R13 proven): 16 k-chunks, 3-stage pipeline ----
    STAGE_LOAD(0, 0);
    asm volatile("cp.async.commit_group;" ::: "memory");
    STAGE_LOAD(1, 16);
    asm volatile("cp.async.commit_group;" ::: "memory");

    for (int t = 0; t < 16; t++) {
        asm volatile("cp.async.wait_group 1;" ::: "memory");
        __syncthreads();
        if (t < 14) {
            STAGE_LOAD((t + 2) % 3, (t + 2) * 16);
        }
        asm volatile("cp.async.commit_group;" ::: "memory");

        const int buf = t % 3;
        const uint32_t Aaddr = smem_base + buf * (ASTG_W * 4) + a_off;
        const uint32_t Baddr = smem_base + (BSTG_BASE + buf * BSTG_W) * 4 + b_off;
#pragma unroll
        for (int k16 = 0; k16 < 2; k16++) {
            uint32_t a0, a1, a2, a3;
            ldmatrix_x4(a0, a1, a2, a3, Aaddr + k16 * 32);
#pragma unroll
            for (int pr = 0; pr < 12; pr++) {
                uint32_t b0, b1, b2, b3;
                ldmatrix_x4(b0, b1, b2, b3, Baddr + pr * 1280 + k16 * 32);
                mma_f16(c[2*pr][0], c[2*pr][1], c[2*pr][2], c[2*pr][3],
                        a0, a1, a2, a3, b0, b1);
                mma_f16(c[2*pr+1][0], c[2*pr+1][1], c[2*pr+1][2], c[2*pr+1][3],
                        a0, a1, a2, a3, b2, b3);
            }
        }
        __syncthreads();
    }

    // ---- Phase 2: Q(x0.125)->Pq, K->Kh [key][d], V->Vt [d][key] ----
    {
        int r0 = wq + gid;
        int r1 = r0 + 8;
#pragma unroll
        for (int nt = 0; nt < 24; nt++) {
            int j = nt * 8 + 2 * tig;
            float b0 = bias_sm[j], b1 = bias_sm[j + 1];
            float v00 = c[nt][0] + b0, v01 = c[nt][1] + b1;
            float v10 = c[nt][2] + b0, v11 = c[nt][3] + b1;
            if (nt < 8) {
                int d2 = j >> 1;
                Pq[r0 * PQP + d2] = pack_h2(v00 * 0.125f, v01 * 0.125f);
                Pq[r1 * PQP + d2] = pack_h2(v10 * 0.125f, v11 * 0.125f);
            } else if (nt < 16) {
                int d2 = (j - 64) >> 1;
                Kh[r0 * KHP + d2] = pack_h2(v00, v01);
                Kh[r1 * KHP + d2] = pack_h2(v10, v11);
            } else {
                int d = j - 128;
                Vth[(size_t)d       * 264 + r0] = __float2half_rn(v00);
                Vth[(size_t)(d + 1) * 264 + r0] = __float2half_rn(v01);
                Vth[(size_t)d       * 264 + r1] = __float2half_rn(v10);
                Vth[(size_t)(d + 1) * 264 + r1] = __float2half_rn(v11);
            }
        }
    }
    __syncthreads();

    // ---- Phase 3: flash attention (R13: ldmatrix K/V, P register trick) ----
    uint32_t qf[4][4];
#pragma unroll
    for (int kt = 0; kt < 4; kt++) {
        int kw = kt * 8;
        qf[kt][0] = Pq[(wq + gid)     * PQP + kw + tig];
        qf[kt][1] = Pq[(wq + gid + 8) * PQP + kw + tig];
        qf[kt][2] = Pq[(wq + gid)     * PQP + kw + tig + 4];
        qf[kt][3] = Pq[(wq + gid + 8) * PQP + kw + tig + 4];
    }
    __syncwarp();

    float o[8][4];
#pragma unroll
    for (int nt = 0; nt < 8; nt++)
#pragma unroll
        for (int r = 0; r < 4; r++) o[nt][r] = 0.f;

    float mrun[2] = { -1e30f, -1e30f };
    float lrun[2] = { 0.f, 0.f };

    for (int kb = 0; kb < 4; kb++) {
        const int kbase = kb * 64;

        float s[8][4];
#pragma unroll
        for (int nt = 0; nt < 8; nt++)
#pragma unroll
            for (int r = 0; r < 4; r++) s[nt][r] = 0.f;

#pragma unroll
        for (int hd = 0; hd < 2; hd++) {
#pragma unroll
            for (int nt = 0; nt < 8; nt++) {
                uint32_t addr = smem_base + KH_BASE * 4 +
                    ((kbase + nt * 8 + (lane & 7)) * 72 + (lane >> 3) * 8 + hd * 32) * 2;
                uint32_t b0, b1, b2, b3;
                ldmatrix_x4(b0, b1, b2, b3, addr);
                mma_f16(s[nt][0], s[nt][1], s[nt][2], s[nt][3],
                        qf[2*hd][0], qf[2*hd][1], qf[2*hd][2], qf[2*hd][3], b0, b1);
                mma_f16(s[nt][0], s[nt][1], s[nt][2], s[nt][3],
                        qf[2*hd+1][0], qf[2*hd+1][1], qf[2*hd+1][2], qf[2*hd+1][3], b2, b3);
            }
        }

        float mloc[2] = { -1e30f, -1e30f };
#pragma unroll
        for (int nt = 0; nt < 8; nt++) {
            mloc[0] = fmaxf(mloc[0], fmaxf(s[nt][0], s[nt][1]));
            mloc[1] = fmaxf(mloc[1], fmaxf(s[nt][2], s[nt][3]));
        }
#pragma unroll
        for (int z = 0; z < 2; z++) {
            mloc[z] = fmaxf(mloc[z], __shfl_xor_sync(0xffffffffu, mloc[z], 1));
            mloc[z] = fmaxf(mloc[z], __shfl_xor_sync(0xffffffffu, mloc[z], 2));
        }
        float scale[2], lsum[2];
#pragma unroll
        for (int z = 0; z < 2; z++) {
            float mnew = fmaxf(mrun[z], mloc[z]);
            scale[z] = __expf(mrun[z] - mnew);
            mrun[z] = mnew;
            lsum[z] = 0.f;
        }
#pragma unroll
        for (int nt = 0; nt < 8; nt++) {
            s[nt][0] = __expf(s[nt][0] - mrun[0]);
            s[nt][1] = __expf(s[nt][1] - mrun[0]);
            s[nt][2] = __expf(s[nt][2] - mrun[1]);
            s[nt][3] = __expf(s[nt][3] - mrun[1]);
            lsum[0] += s[nt][0] + s[nt][1];
            lsum[1] += s[nt][2] + s[nt][3];
        }
#pragma unroll
        for (int z = 0; z < 2; z++) {
            lsum[z] += __shfl_xor_sync(0xffffffffu, lsum[z], 1);
            lsum[z] += __shfl_xor_sync(0xffffffffu, lsum[z], 2);
            lrun[z] = lrun[z] * scale[z] + lsum[z];
        }
#pragma unroll
        for (int nt = 0; nt < 8; nt++) {
            o[nt][0] *= scale[0];
            o[nt][1] *= scale[0];
            o[nt][2] *= scale[1];
            o[nt][3] *= scale[1];
        }

        uint32_t pf[4][4];
#pragma unroll
        for (int kt = 0; kt < 4; kt++) {
            pf[kt][0] = pack_h2(s[2*kt][0],   s[2*kt][1]);
            pf[kt][1] = pack_h2(s[2*kt][2],   s[2*kt][3]);
            pf[kt][2] = pack_h2(s[2*kt+1][0], s[2*kt+1][1]);
            pf[kt][3] = pack_h2(s[2*kt+1][2], s[2*kt+1][3]);
        }

#pragma unroll
        for (int hk = 0; hk < 2; hk++) {
#pragma unroll
            for (int nt = 0; nt < 8; nt++) {
                uint32_t addr = smem_base + VT_BASE * 4 +
                    ((nt * 8 + (lane & 7)) * 264 + kbase + (lane >> 3) * 8 + hk * 32) * 2;
                uint32_t b0, b1, b2, b3;
                ldmatrix_x4(b0, b1, b2, b3, addr);
                mma_f16(o[nt][0], o[nt][1], o[nt][2], o[nt][3],
                        pf[2*hk][0], pf[2*hk][1], pf[2*hk][2], pf[2*hk][3], b0, b1);
                mma_f16(o[nt][0], o[nt][1], o[nt][2], o[nt][3],
                        pf[2*hk+1][0], pf[2*hk+1][1], pf[2*hk+1][2], pf[2*hk+1][3], b2, b3);
            }
        }
    }

    // ---- epilogue: normalize, residual, scatter to out + fp16 xh write ----
    float inv[2] = { 1.f / lrun[0], 1.f / lrun[1] };

    const int b  = n >> 4;
    const int by = (n >> 2) & 3;
    const int bx = n & 3;

#pragma unroll
    for (int hh = 0; hh < 2; hh++) {
        int q = wq + gid + 8 * hh;
        int f  = q >> 6;
        int ry = (q >> 3) & 7;
        int rx = q & 7;
        int gr = by * 8 + ry;
        int gc = bx * 8 + rx;
        int frame = pass + f;
        size_t rowoff = (((((size_t)b * 8 + frame) * 32 + gr) * 32 + gc) * CH) + h * DM;
        const float* res = ((pass == 0 || f == 3) ? xin : (const float*)outbuf) + rowoff;
        float* dst = outbuf + rowoff;
        // fp16 copy for the NEXT pass (rows f>=1 become its rows 0..191)
        __half2* xd = (f >= 1)
            ? xw + ((size_t)n * 192 + (q - 64)) * (CH / 2) + h * (DM / 2)
            : (__half2*)0;
        float sc = inv[hh];
#pragma unroll
        for (int nt = 0; nt < 8; nt++) {
            int d = nt * 8 + 2 * tig;
            float2 r = *(const float2*)(res + d);
            float2 ov;
            ov.x = o[nt][2 * hh + 0] * sc + r.x;
            ov.y = o[nt][2 * hh + 1] * sc + r.y;
            *(float2*)(dst + d) = ov;
            if (f >= 1) {
                uint32_t p = pack_h2(ov.x, ov.y);
                xd[d >> 1] = *(__half2*)&p;
            }
        }
    }
}

// ---------------------------------------------------------------------------
extern "C" void kernel_launch(void* const* d_in, const int* in_sizes, int n_in,
                              void* d_out, int out_size)
{
    const float* x  = (const float*)d_in[0];
    const float* Wq = (const float*)d_in[1];
    const float* Wk = (const float*)d_in[2];
    const float* Wv = (const float*)d_in[3];
    const float* bq = (const float*)d_in[4];
    const float* bk = (const float*)d_in[5];
    const float* bv = (const float*)d_in[6];
    float* out = (float*)d_out;

    cudaFuncSetAttribute(fused_kernel, cudaFuncAttributeMaxDynamicSharedMemorySize,
                         FUSED_SMEM);

    wtrans_kernel<<<(NH * JC * (CH / 2) + 255) / 256, 256>>>(Wq, Wk, Wv);
    xprep_kernel<<<(NWIN * 512 * CH / 4 + 255) / 256, 256>>>(x);

    for (int pass = 0; pass <= 4; pass++) {
        fused_kernel<<<NWIN * NH, 512, FUSED_SMEM>>>(out, x, pass, bq, bk, bv);
    }
}

// round 15
// speedup vs baseline: 1.0193x; 1.0193x over previous
#include <cuda_runtime.h>
#include <cuda_fp16.h>
#include <math.h>
#include <stdint.h>

// ---------------------------------------------------------------------------
// SpaceTimeLocalSelfAttention — R15: R14 + 2-D GEMM warp tiling (8m x 2n,
//   B smem redundancy halved) + single barrier per k-iter (provably safe).
// B=4, T=8, H=W=32, C=512, NH=8, DM=64, KT=4, KS=8
// ---------------------------------------------------------------------------

#define NWIN   64
#define SEQ    256
#define CH     512
#define NH     8
#define DM     64
#define JC     192

// attention smem (32-bit words) — R13/R14 proven layouts
#define PQP    36
#define KHP    36
#define VTP    132
#define PQ_W   (SEQ * PQP)
#define KH_BASE PQ_W
#define KH_W   (SEQ * KHP)
#define VT_BASE (KH_BASE + KH_W)
#define VT_W   (DM * VTP)

// GEMM staging overlays (3 stages)
#define ASTG_W (SEQ * 20)
#define BSTG_W (JC * 20)
#define BSTG_BASE (3 * ASTG_W)
#define FUSED_SMEM ((BSTG_BASE + 3 * BSTG_W) * 4)

__device__ __half2 g_xf [NWIN * 512 * (CH / 2)];   // [n][f*64+rr][c] raw x
__device__ __half2 g_xha[NWIN * 192 * (CH / 2)];   // ping-pong attended windows
__device__ __half2 g_xhb[NWIN * 192 * (CH / 2)];
__device__ __half2 g_wh [NH * JC * (CH / 2)];      // [h][j][k2]

__device__ __forceinline__ uint32_t smem_u32(const void* p) {
    uint32_t a;
    asm("{ .reg .u64 t; cvta.to.shared.u64 t, %1; cvt.u32.u64 %0, t; }"
        : "=r"(a) : "l"(p));
    return a;
}
__device__ __forceinline__ void cp_async16(uint32_t dst, const void* src) {
    asm volatile("cp.async.cg.shared.global [%0], [%1], 16;"
                 :: "r"(dst), "l"(src) : "memory");
}
__device__ __forceinline__ void ldmatrix_x4(uint32_t& r0, uint32_t& r1,
                                            uint32_t& r2, uint32_t& r3, uint32_t addr)
{
    asm volatile("ldmatrix.sync.aligned.m8n8.x4.shared.b16 {%0,%1,%2,%3}, [%4];"
                 : "=r"(r0), "=r"(r1), "=r"(r2), "=r"(r3) : "r"(addr));
}
__device__ __forceinline__ void mma_f16(float& c0, float& c1, float& c2, float& c3,
                                        uint32_t a0, uint32_t a1, uint32_t a2, uint32_t a3,
                                        uint32_t b0, uint32_t b1)
{
    asm volatile(
        "mma.sync.aligned.m16n8k16.row.col.f32.f16.f16.f32 "
        "{%0,%1,%2,%3}, {%4,%5,%6,%7}, {%8,%9}, {%0,%1,%2,%3};"
        : "+f"(c0), "+f"(c1), "+f"(c2), "+f"(c3)
        : "r"(a0), "r"(a1), "r"(a2), "r"(a3), "r"(b0), "r"(b1));
}
__device__ __forceinline__ uint32_t pack_h2(float x, float y) {
    __half2 h = __float22half2_rn(make_float2(x, y));
    return *(uint32_t*)&h;
}

// ---------------------------------------------------------------------------
__global__ void wtrans_kernel(const float* __restrict__ Wq,
                              const float* __restrict__ Wk,
                              const float* __restrict__ Wv)
{
    int idx = blockIdx.x * blockDim.x + threadIdx.x;
    if (idx >= NH * JC * (CH / 2)) return;
    int k2 = idx & 255;
    int j  = (idx >> 8) % JC;
    int h  = idx / (JC * 256);
    int w  = j >> 6;
    int dm = j & 63;
    const float* W = (w == 0) ? Wq : (w == 1) ? Wk : Wv;
    float v0 = W[((size_t)h * CH + 2 * k2)     * DM + dm];
    float v1 = W[((size_t)h * CH + 2 * k2 + 1) * DM + dm];
    g_wh[idx] = __float22half2_rn(make_float2(v0, v1));
}

// ---------------------------------------------------------------------------
__global__ void xprep_kernel(const float* __restrict__ x)
{
    int idx = blockIdx.x * blockDim.x + threadIdx.x;
    if (idx >= (NWIN * 512 * CH) / 4) return;
    int e = idx * 4;
    int c = e & (CH - 1);
    int r = (e >> 9) & 511;
    int n = e >> 18;
    int f  = r >> 6;
    int ry = (r >> 3) & 7;
    int rx = r & 7;
    int b  = n >> 4;
    int by = (n >> 2) & 3;
    int bx = n & 3;
    const float* src = x + (((((size_t)b * 8 + f) * 32 + by * 8 + ry) * 32
                             + bx * 8 + rx) * CH + c);
    float4 v = *(const float4*)src;
    g_xf[e / 2]     = __float22half2_rn(make_float2(v.x, v.y));
    g_xf[e / 2 + 1] = __float22half2_rn(make_float2(v.z, v.w));
}

// ---------------------------------------------------------------------------
__global__ __launch_bounds__(512, 1) void fused_kernel(
    float* __restrict__ outbuf, const float* __restrict__ xin, int pass,
    const float* __restrict__ bq, const float* __restrict__ bk,
    const float* __restrict__ bv)
{
    const int n = blockIdx.x >> 3;
    const int h = blockIdx.x & 7;

    extern __shared__ __align__(16) uint32_t sm[];
    uint32_t* Pq  = sm;
    uint32_t* Kh  = sm + KH_BASE;
    __half*   Vth = (__half*)(sm + VT_BASE);

    __shared__ float bias_sm[JC];

    const int tid = threadIdx.x;
    const int lane = tid & 31;
    const int gid = lane >> 2;
    const int tig = lane & 3;
    const int wid = tid >> 5;
    const int wq = wid * 16;            // attention rows
    const int mw = wid & 7;             // GEMM m-warp
    const int nw = wid >> 3;            // GEMM n-warp

    if (tid < JC) {
        int dm = tid & 63;
        int wsel = tid >> 6;
        const float* bb = (wsel == 0) ? bq : (wsel == 1) ? bk : bv;
        bias_sm[tid] = bb[h * DM + dm];
    }

    __half2* xw = (pass & 1) ? g_xha : g_xhb;
    const __half2* xr = (pass & 1) ? g_xhb : g_xha;
    const __half2* Alo = (pass == 0)
        ? g_xf + (size_t)n * 512 * (CH / 2)
        : xr   + (size_t)n * 192 * (CH / 2);
    const __half2* Ahi = g_xf + ((size_t)n * 512 + (pass + 3) * 64 - 192) * (CH / 2);
    const __half2* Bbase = g_wh + (size_t)h * JC * (CH / 2);

    const uint32_t smem_base = smem_u32(sm);
    uint32_t a_off[2];
#pragma unroll
    for (int mt = 0; mt < 2; mt++)
        a_off[mt] = (((mw * 32 + mt * 16 + (lane & 15)) * 40) + ((lane >> 4) << 3)) * 2;
    const uint32_t b_off = (((nw * 96 + (lane & 7) + ((lane >> 4) << 3)) * 40) +
                            (((lane >> 3) & 1) << 3)) * 2;

    float c[2][12][4];
#pragma unroll
    for (int mt = 0; mt < 2; mt++)
#pragma unroll
        for (int nt = 0; nt < 12; nt++)
#pragma unroll
            for (int r = 0; r < 4; r++) c[mt][nt][r] = 0.f;

#define STAGE_LOAD(st, kc2)                                                     \
    {                                                                           \
        uint32_t ab = smem_base + (st) * (ASTG_W * 4);                          \
        _Pragma("unroll")                                                       \
        for (int i = 0; i < 2; i++) {                                           \
            int ck = tid + 512 * i;                                             \
            int row = ck >> 2, cg = ck & 3;                                     \
            const __half2* asrc = (row < 192 ? Alo : Ahi);                      \
            cp_async16(ab + (row * 20 + cg * 4) * 4,                            \
                       asrc + (size_t)row * (CH / 2) + (kc2) + cg * 4);         \
        }                                                                       \
        uint32_t bb2 = smem_base + (BSTG_BASE + (st) * BSTG_W) * 4;             \
        for (int ck = tid; ck < 768; ck += 512) {                               \
            int j = ck >> 2, cg = ck & 3;                                       \
            cp_async16(bb2 + (j * 20 + cg * 4) * 4,                             \
                       Bbase + (size_t)j * (CH / 2) + (kc2) + cg * 4);          \
        }                                                                       \
    }

    // ---- Phase 1: GEMM, 16 k-chunks, 3-stage pipeline, ONE sync/iter ----
    STAGE_LOAD(0, 0);
    asm volatile("cp.async.commit_group;" ::: "memory");
    STAGE_LOAD(1, 16);
    asm volatile("cp.async.commit_group;" ::: "memory");

    for (int t = 0; t < 16; t++) {
        asm volatile("cp.async.wait_group 1;" ::: "memory");
        __syncthreads();
        if (t < 14) {
            STAGE_LOAD((t + 2) % 3, (t + 2) * 16);
        }
        asm volatile("cp.async.commit_group;" ::: "memory");

        const int buf = t % 3;
        const uint32_t Ast = smem_base + buf * (ASTG_W * 4);
        const uint32_t Bst = smem_base + (BSTG_BASE + buf * BSTG_W) * 4;
#pragma unroll
        for (int k16 = 0; k16 < 2; k16++) {
            uint32_t a[2][4];
#pragma unroll
            for (int mt = 0; mt < 2; mt++)
                ldmatrix_x4(a[mt][0], a[mt][1], a[mt][2], a[mt][3],
                            Ast + a_off[mt] + k16 * 32);
#pragma unroll
            for (int pr = 0; pr < 6; pr++) {
                uint32_t b0, b1, b2, b3;
                ldmatrix_x4(b0, b1, b2, b3, Bst + b_off + pr * 1280 + k16 * 32);
#pragma unroll
                for (int mt = 0; mt < 2; mt++) {
                    mma_f16(c[mt][2*pr][0], c[mt][2*pr][1], c[mt][2*pr][2], c[mt][2*pr][3],
                            a[mt][0], a[mt][1], a[mt][2], a[mt][3], b0, b1);
                    mma_f16(c[mt][2*pr+1][0], c[mt][2*pr+1][1], c[mt][2*pr+1][2], c[mt][2*pr+1][3],
                            a[mt][0], a[mt][1], a[mt][2], a[mt][3], b2, b3);
                }
            }
        }
        // no bottom barrier: stage (t+2)%3 == stage (t-1)%3, already retired
        // by the top-of-iter sync (every warp passed compute t-1 before it).
    }
    asm volatile("cp.async.wait_group 0;" ::: "memory");
    __syncthreads();   // protect phase-2 overlay writes against last GEMM reads

    // ---- Phase 2: route c -> Pq (x0.125) / Kh [key][d] / Vt [d][key] ----
#pragma unroll
    for (int mt = 0; mt < 2; mt++) {
        int r0 = mw * 32 + mt * 16 + gid;
        int r1 = r0 + 8;
#pragma unroll
        for (int nt = 0; nt < 12; nt++) {
            int j = nw * 96 + nt * 8 + 2 * tig;
            float b0 = bias_sm[j], b1 = bias_sm[j + 1];
            float v00 = c[mt][nt][0] + b0, v01 = c[mt][nt][1] + b1;
            float v10 = c[mt][nt][2] + b0, v11 = c[mt][nt][3] + b1;
            if (j < 64) {
                int d2 = j >> 1;
                Pq[r0 * PQP + d2] = pack_h2(v00 * 0.125f, v01 * 0.125f);
                Pq[r1 * PQP + d2] = pack_h2(v10 * 0.125f, v11 * 0.125f);
            } else if (j < 128) {
                int d2 = (j - 64) >> 1;
                Kh[r0 * KHP + d2] = pack_h2(v00, v01);
                Kh[r1 * KHP + d2] = pack_h2(v10, v11);
            } else {
                int d = j - 128;
                Vth[(size_t)d       * 264 + r0] = __float2half_rn(v00);
                Vth[(size_t)(d + 1) * 264 + r0] = __float2half_rn(v01);
                Vth[(size_t)d       * 264 + r1] = __float2half_rn(v10);
                Vth[(size_t)(d + 1) * 264 + r1] = __float2half_rn(v11);
            }
        }
    }
    __syncthreads();

    // ---- Phase 3: flash attention (R13 proven) ----
    uint32_t qf[4][4];
#pragma unroll
    for (int kt = 0; kt < 4; kt++) {
        int kw = kt * 8;
        qf[kt][0] = Pq[(wq + gid)     * PQP + kw + tig];
        qf[kt][1] = Pq[(wq + gid + 8) * PQP + kw + tig];
        qf[kt][2] = Pq[(wq + gid)     * PQP + kw + tig + 4];
        qf[kt][3] = Pq[(wq + gid + 8) * PQP + kw + tig + 4];
    }
    __syncwarp();

    float o[8][4];
#pragma unroll
    for (int nt = 0; nt < 8; nt++)
#pragma unroll
        for (int r = 0; r < 4; r++) o[nt][r] = 0.f;

    float mrun[2] = { -1e30f, -1e30f };
    float lrun[2] = { 0.f, 0.f };

    for (int kb = 0; kb < 4; kb++) {
        const int kbase = kb * 64;

        float s[8][4];
#pragma unroll
        for (int nt = 0; nt < 8; nt++)
#pragma unroll
            for (int r = 0; r < 4; r++) s[nt][r] = 0.f;

#pragma unroll
        for (int hd = 0; hd < 2; hd++) {
#pragma unroll
            for (int nt = 0; nt < 8; nt++) {
                uint32_t addr = smem_base + KH_BASE * 4 +
                    ((kbase + nt * 8 + (lane & 7)) * 72 + (lane >> 3) * 8 + hd * 32) * 2;
                uint32_t b0, b1, b2, b3;
                ldmatrix_x4(b0, b1, b2, b3, addr);
                mma_f16(s[nt][0], s[nt][1], s[nt][2], s[nt][3],
                        qf[2*hd][0], qf[2*hd][1], qf[2*hd][2], qf[2*hd][3], b0, b1);
                mma_f16(s[nt][0], s[nt][1], s[nt][2], s[nt][3],
                        qf[2*hd+1][0], qf[2*hd+1][1], qf[2*hd+1][2], qf[2*hd+1][3], b2, b3);
            }
        }

        float mloc[2] = { -1e30f, -1e30f };
#pragma unroll
        for (int nt = 0; nt < 8; nt++) {
            mloc[0] = fmaxf(mloc[0], fmaxf(s[nt][0], s[nt][1]));
            mloc[1] = fmaxf(mloc[1], fmaxf(s[nt][2], s[nt][3]));
        }
#pragma unroll
        for (int z = 0; z < 2; z++) {
            mloc[z] = fmaxf(mloc[z], __shfl_xor_sync(0xffffffffu, mloc[z], 1));
            mloc[z] = fmaxf(mloc[z], __shfl_xor_sync(0xffffffffu, mloc[z], 2));
        }
        float scale[2], lsum[2];
#pragma unroll
        for (int z = 0; z < 2; z++) {
            float mnew = fmaxf(mrun[z], mloc[z]);
            scale[z] = __expf(mrun[z] - mnew);
            mrun[z] = mnew;
            lsum[z] = 0.f;
        }
#pragma unroll
        for (int nt = 0; nt < 8; nt++) {
            s[nt][0] = __expf(s[nt][0] - mrun[0]);
            s[nt][1] = __expf(s[nt][1] - mrun[0]);
            s[nt][2] = __expf(s[nt][2] - mrun[1]);
            s[nt][3] = __expf(s[nt][3] - mrun[1]);
            lsum[0] += s[nt][0] + s[nt][1];
            lsum[1] += s[nt][2] + s[nt][3];
        }
#pragma unroll
        for (int z = 0; z < 2; z++) {
            lsum[z] += __shfl_xor_sync(0xffffffffu, lsum[z], 1);
            lsum[z] += __shfl_xor_sync(0xffffffffu, lsum[z], 2);
            lrun[z] = lrun[z] * scale[z] + lsum[z];
        }
#pragma unroll
        for (int nt = 0; nt < 8; nt++) {
            o[nt][0] *= scale[0];
            o[nt][1] *= scale[0];
            o[nt][2] *= scale[1];
            o[nt][3] *= scale[1];
        }

        uint32_t pf[4][4];
#pragma unroll
        for (int kt = 0; kt < 4; kt++) {
            pf[kt][0] = pack_h2(s[2*kt][0],   s[2*kt][1]);
            pf[kt][1] = pack_h2(s[2*kt][2],   s[2*kt][3]);
            pf[kt][2] = pack_h2(s[2*kt+1][0], s[2*kt+1][1]);
            pf[kt][3] = pack_h2(s[2*kt+1][2], s[2*kt+1][3]);
        }

#pragma unroll
        for (int hk = 0; hk < 2; hk++) {
#pragma unroll
            for (int nt = 0; nt < 8; nt++) {
                uint32_t addr = smem_base + VT_BASE * 4 +
                    ((nt * 8 + (lane & 7)) * 264 + kbase + (lane >> 3) * 8 + hk * 32) * 2;
                uint32_t b0, b1, b2, b3;
                ldmatrix_x4(b0, b1, b2, b3, addr);
                mma_f16(o[nt][0], o[nt][1], o[nt][2], o[nt][3],
                        pf[2*hk][0], pf[2*hk][1], pf[2*hk][2], pf[2*hk][3], b0, b1);
                mma_f16(o[nt][0], o[nt][1], o[nt][2], o[nt][3],
                        pf[2*hk+1][0], pf[2*hk+1][1], pf[2*hk+1][2], pf[2*hk+1][3], b2, b3);
            }
        }
    }

    // ---- epilogue: normalize, residual, scatter + fp16 xh write ----
    float inv[2] = { 1.f / lrun[0], 1.f / lrun[1] };

    const int b  = n >> 4;
    const int by = (n >> 2) & 3;
    const int bx = n & 3;

#pragma unroll
    for (int hh = 0; hh < 2; hh++) {
        int q = wq + gid + 8 * hh;
        int f  = q >> 6;
        int ry = (q >> 3) & 7;
        int rx = q & 7;
        int gr = by * 8 + ry;
        int gc = bx * 8 + rx;
        int frame = pass + f;
        size_t rowoff = (((((size_t)b * 8 + frame) * 32 + gr) * 32 + gc) * CH) + h * DM;
        const float* res = ((pass == 0 || f == 3) ? xin : (const float*)outbuf) + rowoff;
        float* dst = outbuf + rowoff;
        __half2* xd = (f >= 1)
            ? xw + ((size_t)n * 192 + (q - 64)) * (CH / 2) + h * (DM / 2)
            : (__half2*)0;
        float sc = inv[hh];
#pragma unroll
        for (int nt = 0; nt < 8; nt++) {
            int d = nt * 8 + 2 * tig;
            float2 r = *(const float2*)(res + d);
            float2 ov;
            ov.x = o[nt][2 * hh + 0] * sc + r.x;
            ov.y = o[nt][2 * hh + 1] * sc + r.y;
            *(float2*)(dst + d) = ov;
            if (f >= 1) {
                uint32_t p = pack_h2(ov.x, ov.y);
                xd[d >> 1] = *(__half2*)&p;
            }
        }
    }
}

// ---------------------------------------------------------------------------
extern "C" void kernel_launch(void* const* d_in, const int* in_sizes, int n_in,
                              void* d_out, int out_size)
{
    const float* x  = (const float*)d_in[0];
    const float* Wq = (const float*)d_in[1];
    const float* Wk = (const float*)d_in[2];
    const float* Wv = (const float*)d_in[3];
    const float* bq = (const float*)d_in[4];
    const float* bk = (const float*)d_in[5];
    const float* bv = (const float*)d_in[6];
    float* out = (float*)d_out;

    cudaFuncSetAttribute(fused_kernel, cudaFuncAttributeMaxDynamicSharedMemorySize,
                         FUSED_SMEM);

    wtrans_kernel<<<(NH * JC * (CH / 2) + 255) / 256, 256>>>(Wq, Wk, Wv);
    xprep_kernel<<<(NWIN * 512 * CH / 4 + 255) / 256, 256>>>(x);

    for (int pass = 0; pass <= 4; pass++) {
        fused_kernel<<<NWIN * NH, 512, FUSED_SMEM>>>(out, x, pass, bq, bk, bv);
    }
}

// round 16
// speedup vs baseline: 1.0393x; 1.0196x over previous
#include <cuda_runtime.h>
#include <cuda_fp16.h>
#include <math.h>
#include <stdint.h>

// ---------------------------------------------------------------------------
// SpaceTimeLocalSelfAttention — R16: R15 + register ping-pong prefetch of
//   ldmatrix fragments (GEMM B, attention K/V) to hide LDSM->MMA latency.
// B=4, T=8, H=W=32, C=512, NH=8, DM=64, KT=4, KS=8
// ---------------------------------------------------------------------------

#define NWIN   64
#define SEQ    256
#define CH     512
#define NH     8
#define DM     64
#define JC     192

// attention smem (32-bit words) — proven layouts
#define PQP    36
#define KHP    36
#define VTP    132
#define PQ_W   (SEQ * PQP)
#define KH_BASE PQ_W
#define KH_W   (SEQ * KHP)
#define VT_BASE (KH_BASE + KH_W)
#define VT_W   (DM * VTP)

// GEMM staging overlays (3 stages)
#define ASTG_W (SEQ * 20)
#define BSTG_W (JC * 20)
#define BSTG_BASE (3 * ASTG_W)
#define FUSED_SMEM ((BSTG_BASE + 3 * BSTG_W) * 4)

__device__ __half2 g_xf [NWIN * 512 * (CH / 2)];
__device__ __half2 g_xha[NWIN * 192 * (CH / 2)];
__device__ __half2 g_xhb[NWIN * 192 * (CH / 2)];
__device__ __half2 g_wh [NH * JC * (CH / 2)];

__device__ __forceinline__ uint32_t smem_u32(const void* p) {
    uint32_t a;
    asm("{ .reg .u64 t; cvta.to.shared.u64 t, %1; cvt.u32.u64 %0, t; }"
        : "=r"(a) : "l"(p));
    return a;
}
__device__ __forceinline__ void cp_async16(uint32_t dst, const void* src) {
    asm volatile("cp.async.cg.shared.global [%0], [%1], 16;"
                 :: "r"(dst), "l"(src) : "memory");
}
__device__ __forceinline__ void ldmatrix_x4(uint32_t& r0, uint32_t& r1,
                                            uint32_t& r2, uint32_t& r3, uint32_t addr)
{
    asm volatile("ldmatrix.sync.aligned.m8n8.x4.shared.b16 {%0,%1,%2,%3}, [%4];"
                 : "=r"(r0), "=r"(r1), "=r"(r2), "=r"(r3) : "r"(addr));
}
__device__ __forceinline__ void mma_f16(float& c0, float& c1, float& c2, float& c3,
                                        uint32_t a0, uint32_t a1, uint32_t a2, uint32_t a3,
                                        uint32_t b0, uint32_t b1)
{
    asm volatile(
        "mma.sync.aligned.m16n8k16.row.col.f32.f16.f16.f32 "
        "{%0,%1,%2,%3}, {%4,%5,%6,%7}, {%8,%9}, {%0,%1,%2,%3};"
        : "+f"(c0), "+f"(c1), "+f"(c2), "+f"(c3)
        : "r"(a0), "r"(a1), "r"(a2), "r"(a3), "r"(b0), "r"(b1));
}
__device__ __forceinline__ uint32_t pack_h2(float x, float y) {
    __half2 h = __float22half2_rn(make_float2(x, y));
    return *(uint32_t*)&h;
}

// ---------------------------------------------------------------------------
__global__ void wtrans_kernel(const float* __restrict__ Wq,
                              const float* __restrict__ Wk,
                              const float* __restrict__ Wv)
{
    int idx = blockIdx.x * blockDim.x + threadIdx.x;
    if (idx >= NH * JC * (CH / 2)) return;
    int k2 = idx & 255;
    int j  = (idx >> 8) % JC;
    int h  = idx / (JC * 256);
    int w  = j >> 6;
    int dm = j & 63;
    const float* W = (w == 0) ? Wq : (w == 1) ? Wk : Wv;
    float v0 = W[((size_t)h * CH + 2 * k2)     * DM + dm];
    float v1 = W[((size_t)h * CH + 2 * k2 + 1) * DM + dm];
    g_wh[idx] = __float22half2_rn(make_float2(v0, v1));
}

// ---------------------------------------------------------------------------
__global__ void xprep_kernel(const float* __restrict__ x)
{
    int idx = blockIdx.x * blockDim.x + threadIdx.x;
    if (idx >= (NWIN * 512 * CH) / 4) return;
    int e = idx * 4;
    int c = e & (CH - 1);
    int r = (e >> 9) & 511;
    int n = e >> 18;
    int f  = r >> 6;
    int ry = (r >> 3) & 7;
    int rx = r & 7;
    int b  = n >> 4;
    int by = (n >> 2) & 3;
    int bx = n & 3;
    const float* src = x + (((((size_t)b * 8 + f) * 32 + by * 8 + ry) * 32
                             + bx * 8 + rx) * CH + c);
    float4 v = *(const float4*)src;
    g_xf[e / 2]     = __float22half2_rn(make_float2(v.x, v.y));
    g_xf[e / 2 + 1] = __float22half2_rn(make_float2(v.z, v.w));
}

// ---------------------------------------------------------------------------
__global__ __launch_bounds__(512, 1) void fused_kernel(
    float* __restrict__ outbuf, const float* __restrict__ xin, int pass,
    const float* __restrict__ bq, const float* __restrict__ bk,
    const float* __restrict__ bv)
{
    const int n = blockIdx.x >> 3;
    const int h = blockIdx.x & 7;

    extern __shared__ __align__(16) uint32_t sm[];
    uint32_t* Pq  = sm;
    uint32_t* Kh  = sm + KH_BASE;
    __half*   Vth = (__half*)(sm + VT_BASE);

    __shared__ float bias_sm[JC];

    const int tid = threadIdx.x;
    const int lane = tid & 31;
    const int gid = lane >> 2;
    const int tig = lane & 3;
    const int wid = tid >> 5;
    const int wq = wid * 16;
    const int mw = wid & 7;
    const int nw = wid >> 3;

    if (tid < JC) {
        int dm = tid & 63;
        int wsel = tid >> 6;
        const float* bb = (wsel == 0) ? bq : (wsel == 1) ? bk : bv;
        bias_sm[tid] = bb[h * DM + dm];
    }

    __half2* xw = (pass & 1) ? g_xha : g_xhb;
    const __half2* xr = (pass & 1) ? g_xhb : g_xha;
    const __half2* Alo = (pass == 0)
        ? g_xf + (size_t)n * 512 * (CH / 2)
        : xr   + (size_t)n * 192 * (CH / 2);
    const __half2* Ahi = g_xf + ((size_t)n * 512 + (pass + 3) * 64 - 192) * (CH / 2);
    const __half2* Bbase = g_wh + (size_t)h * JC * (CH / 2);

    const uint32_t smem_base = smem_u32(sm);
    uint32_t a_off[2];
#pragma unroll
    for (int mt = 0; mt < 2; mt++)
        a_off[mt] = (((mw * 32 + mt * 16 + (lane & 15)) * 40) + ((lane >> 4) << 3)) * 2;
    const uint32_t b_off = (((nw * 96 + (lane & 7) + ((lane >> 4) << 3)) * 40) +
                            (((lane >> 3) & 1) << 3)) * 2;

    float c[2][12][4];
#pragma unroll
    for (int mt = 0; mt < 2; mt++)
#pragma unroll
        for (int nt = 0; nt < 12; nt++)
#pragma unroll
            for (int r = 0; r < 4; r++) c[mt][nt][r] = 0.f;

#define STAGE_LOAD(st, kc2)                                                     \
    {                                                                           \
        uint32_t ab = smem_base + (st) * (ASTG_W * 4);                          \
        _Pragma("unroll")                                                       \
        for (int i = 0; i < 2; i++) {                                           \
            int ck = tid + 512 * i;                                             \
            int row = ck >> 2, cg = ck & 3;                                     \
            const __half2* asrc = (row < 192 ? Alo : Ahi);                      \
            cp_async16(ab + (row * 20 + cg * 4) * 4,                            \
                       asrc + (size_t)row * (CH / 2) + (kc2) + cg * 4);         \
        }                                                                       \
        uint32_t bb2 = smem_base + (BSTG_BASE + (st) * BSTG_W) * 4;             \
        for (int ck = tid; ck < 768; ck += 512) {                               \
            int j = ck >> 2, cg = ck & 3;                                       \
            cp_async16(bb2 + (j * 20 + cg * 4) * 4,                             \
                       Bbase + (size_t)j * (CH / 2) + (kc2) + cg * 4);          \
        }                                                                       \
    }

    // ---- Phase 1: GEMM, 16 k-chunks, 3-stage cp.async, prefetched frags ----
    STAGE_LOAD(0, 0);
    asm volatile("cp.async.commit_group;" ::: "memory");
    STAGE_LOAD(1, 16);
    asm volatile("cp.async.commit_group;" ::: "memory");

    for (int t = 0; t < 16; t++) {
        asm volatile("cp.async.wait_group 1;" ::: "memory");
        __syncthreads();
        if (t < 14) {
            STAGE_LOAD((t + 2) % 3, (t + 2) * 16);
        }
        asm volatile("cp.async.commit_group;" ::: "memory");

        const int buf = t % 3;
        const uint32_t Ast = smem_base + buf * (ASTG_W * 4);
        const uint32_t Bfb = smem_base + (BSTG_BASE + buf * BSTG_W) * 4 + b_off;
#pragma unroll
        for (int k16 = 0; k16 < 2; k16++) {
            uint32_t a[2][4];
#pragma unroll
            for (int mt = 0; mt < 2; mt++)
                ldmatrix_x4(a[mt][0], a[mt][1], a[mt][2], a[mt][3],
                            Ast + a_off[mt] + k16 * 32);
            uint32_t bbf[2][4];
            ldmatrix_x4(bbf[0][0], bbf[0][1], bbf[0][2], bbf[0][3],
                        Bfb + k16 * 32);              // pr = 0
#pragma unroll
            for (int pr = 0; pr < 6; pr++) {
                const int cur = pr & 1;
                if (pr < 5)
                    ldmatrix_x4(bbf[cur ^ 1][0], bbf[cur ^ 1][1],
                                bbf[cur ^ 1][2], bbf[cur ^ 1][3],
                                Bfb + (pr + 1) * 1280 + k16 * 32);
#pragma unroll
                for (int mt = 0; mt < 2; mt++) {
                    mma_f16(c[mt][2*pr][0], c[mt][2*pr][1], c[mt][2*pr][2], c[mt][2*pr][3],
                            a[mt][0], a[mt][1], a[mt][2], a[mt][3],
                            bbf[cur][0], bbf[cur][1]);
                    mma_f16(c[mt][2*pr+1][0], c[mt][2*pr+1][1], c[mt][2*pr+1][2], c[mt][2*pr+1][3],
                            a[mt][0], a[mt][1], a[mt][2], a[mt][3],
                            bbf[cur][2], bbf[cur][3]);
                }
            }
        }
    }
    asm volatile("cp.async.wait_group 0;" ::: "memory");
    __syncthreads();

    // ---- Phase 2: route c -> Pq (x0.125) / Kh [key][d] / Vt [d][key] ----
#pragma unroll
    for (int mt = 0; mt < 2; mt++) {
        int r0 = mw * 32 + mt * 16 + gid;
        int r1 = r0 + 8;
#pragma unroll
        for (int nt = 0; nt < 12; nt++) {
            int j = nw * 96 + nt * 8 + 2 * tig;
            float b0 = bias_sm[j], b1 = bias_sm[j + 1];
            float v00 = c[mt][nt][0] + b0, v01 = c[mt][nt][1] + b1;
            float v10 = c[mt][nt][2] + b0, v11 = c[mt][nt][3] + b1;
            if (j < 64) {
                int d2 = j >> 1;
                Pq[r0 * PQP + d2] = pack_h2(v00 * 0.125f, v01 * 0.125f);
                Pq[r1 * PQP + d2] = pack_h2(v10 * 0.125f, v11 * 0.125f);
            } else if (j < 128) {
                int d2 = (j - 64) >> 1;
                Kh[r0 * KHP + d2] = pack_h2(v00, v01);
                Kh[r1 * KHP + d2] = pack_h2(v10, v11);
            } else {
                int d = j - 128;
                Vth[(size_t)d       * 264 + r0] = __float2half_rn(v00);
                Vth[(size_t)(d + 1) * 264 + r0] = __float2half_rn(v01);
                Vth[(size_t)d       * 264 + r1] = __float2half_rn(v10);
                Vth[(size_t)(d + 1) * 264 + r1] = __float2half_rn(v11);
            }
        }
    }
    __syncthreads();

    // ---- Phase 3: flash attention, prefetched K/V fragments ----
    uint32_t qf[4][4];
#pragma unroll
    for (int kt = 0; kt < 4; kt++) {
        int kw = kt * 8;
        qf[kt][0] = Pq[(wq + gid)     * PQP + kw + tig];
        qf[kt][1] = Pq[(wq + gid + 8) * PQP + kw + tig];
        qf[kt][2] = Pq[(wq + gid)     * PQP + kw + tig + 4];
        qf[kt][3] = Pq[(wq + gid + 8) * PQP + kw + tig + 4];
    }
    __syncwarp();

    float o[8][4];
#pragma unroll
    for (int nt = 0; nt < 8; nt++)
#pragma unroll
        for (int r = 0; r < 4; r++) o[nt][r] = 0.f;

    float mrun[2] = { -1e30f, -1e30f };
    float lrun[2] = { 0.f, 0.f };

    // address helpers (byte addresses)
#define KH_ADDR(kbase, hd, nt) (smem_base + KH_BASE * 4 + \
    (((kbase) + (nt) * 8 + (lane & 7)) * 72 + (lane >> 3) * 8 + (hd) * 32) * 2)
#define VT_ADDR(kbase, hk, nt) (smem_base + VT_BASE * 4 + \
    (((nt) * 8 + (lane & 7)) * 264 + (kbase) + (lane >> 3) * 8 + (hk) * 32) * 2)

    for (int kb = 0; kb < 4; kb++) {
        const int kbase = kb * 64;

        float s[8][4];
#pragma unroll
        for (int nt = 0; nt < 8; nt++)
#pragma unroll
            for (int r = 0; r < 4; r++) s[nt][r] = 0.f;

        // S = Q K^T : 16 flattened iterations (hd major), ping-pong frags
        {
            uint32_t kf[2][4];
            ldmatrix_x4(kf[0][0], kf[0][1], kf[0][2], kf[0][3],
                        KH_ADDR(kbase, 0, 0));
#pragma unroll
            for (int it = 0; it < 16; it++) {
                const int hd = it >> 3, nt = it & 7;
                const int cur = it & 1;
                if (it < 15) {
                    const int it2 = it + 1;
                    ldmatrix_x4(kf[cur ^ 1][0], kf[cur ^ 1][1],
                                kf[cur ^ 1][2], kf[cur ^ 1][3],
                                KH_ADDR(kbase, it2 >> 3, it2 & 7));
                }
                mma_f16(s[nt][0], s[nt][1], s[nt][2], s[nt][3],
                        qf[2*hd][0], qf[2*hd][1], qf[2*hd][2], qf[2*hd][3],
                        kf[cur][0], kf[cur][1]);
                mma_f16(s[nt][0], s[nt][1], s[nt][2], s[nt][3],
                        qf[2*hd+1][0], qf[2*hd+1][1], qf[2*hd+1][2], qf[2*hd+1][3],
                        kf[cur][2], kf[cur][3]);
            }
        }

        float mloc[2] = { -1e30f, -1e30f };
#pragma unroll
        for (int nt = 0; nt < 8; nt++) {
            mloc[0] = fmaxf(mloc[0], fmaxf(s[nt][0], s[nt][1]));
            mloc[1] = fmaxf(mloc[1], fmaxf(s[nt][2], s[nt][3]));
        }
#pragma unroll
        for (int z = 0; z < 2; z++) {
            mloc[z] = fmaxf(mloc[z], __shfl_xor_sync(0xffffffffu, mloc[z], 1));
            mloc[z] = fmaxf(mloc[z], __shfl_xor_sync(0xffffffffu, mloc[z], 2));
        }
        float scale[2], lsum[2];
#pragma unroll
        for (int z = 0; z < 2; z++) {
            float mnew = fmaxf(mrun[z], mloc[z]);
            scale[z] = __expf(mrun[z] - mnew);
            mrun[z] = mnew;
            lsum[z] = 0.f;
        }
#pragma unroll
        for (int nt = 0; nt < 8; nt++) {
            s[nt][0] = __expf(s[nt][0] - mrun[0]);
            s[nt][1] = __expf(s[nt][1] - mrun[0]);
            s[nt][2] = __expf(s[nt][2] - mrun[1]);
            s[nt][3] = __expf(s[nt][3] - mrun[1]);
            lsum[0] += s[nt][0] + s[nt][1];
            lsum[1] += s[nt][2] + s[nt][3];
        }
#pragma unroll
        for (int z = 0; z < 2; z++) {
            lsum[z] += __shfl_xor_sync(0xffffffffu, lsum[z], 1);
            lsum[z] += __shfl_xor_sync(0xffffffffu, lsum[z], 2);
            lrun[z] = lrun[z] * scale[z] + lsum[z];
        }
#pragma unroll
        for (int nt = 0; nt < 8; nt++) {
            o[nt][0] *= scale[0];
            o[nt][1] *= scale[0];
            o[nt][2] *= scale[1];
            o[nt][3] *= scale[1];
        }

        uint32_t pf[4][4];
#pragma unroll
        for (int kt = 0; kt < 4; kt++) {
            pf[kt][0] = pack_h2(s[2*kt][0],   s[2*kt][1]);
            pf[kt][1] = pack_h2(s[2*kt][2],   s[2*kt][3]);
            pf[kt][2] = pack_h2(s[2*kt+1][0], s[2*kt+1][1]);
            pf[kt][3] = pack_h2(s[2*kt+1][2], s[2*kt+1][3]);
        }

        // O += P V : 16 flattened iterations (hk major), ping-pong frags
        {
            uint32_t vf[2][4];
            ldmatrix_x4(vf[0][0], vf[0][1], vf[0][2], vf[0][3],
                        VT_ADDR(kbase, 0, 0));
#pragma unroll
            for (int it = 0; it < 16; it++) {
                const int hk = it >> 3, nt = it & 7;
                const int cur = it & 1;
                if (it < 15) {
                    const int it2 = it + 1;
                    ldmatrix_x4(vf[cur ^ 1][0], vf[cur ^ 1][1],
                                vf[cur ^ 1][2], vf[cur ^ 1][3],
                                VT_ADDR(kbase, it2 >> 3, it2 & 7));
                }
                mma_f16(o[nt][0], o[nt][1], o[nt][2], o[nt][3],
                        pf[2*hk][0], pf[2*hk][1], pf[2*hk][2], pf[2*hk][3],
                        vf[cur][0], vf[cur][1]);
                mma_f16(o[nt][0], o[nt][1], o[nt][2], o[nt][3],
                        pf[2*hk+1][0], pf[2*hk+1][1], pf[2*hk+1][2], pf[2*hk+1][3],
                        vf[cur][2], vf[cur][3]);
            }
        }
    }

    // ---- epilogue: normalize, residual, scatter + fp16 xh write ----
    float inv[2] = { 1.f / lrun[0], 1.f / lrun[1] };

    const int b  = n >> 4;
    const int by = (n >> 2) & 3;
    const int bx = n & 3;

#pragma unroll
    for (int hh = 0; hh < 2; hh++) {
        int q = wq + gid + 8 * hh;
        int f  = q >> 6;
        int ry = (q >> 3) & 7;
        int rx = q & 7;
        int gr = by * 8 + ry;
        int gc = bx * 8 + rx;
        int frame = pass + f;
        size_t rowoff = (((((size_t)b * 8 + frame) * 32 + gr) * 32 + gc) * CH) + h * DM;
        const float* res = ((pass == 0 || f == 3) ? xin : (const float*)outbuf) + rowoff;
        float* dst = outbuf + rowoff;
        __half2* xd = (f >= 1)
            ? xw + ((size_t)n * 192 + (q - 64)) * (CH / 2) + h * (DM / 2)
            : (__half2*)0;
        float sc = inv[hh];
#pragma unroll
        for (int nt = 0; nt < 8; nt++) {
            int d = nt * 8 + 2 * tig;
            float2 r = *(const float2*)(res + d);
            float2 ov;
            ov.x = o[nt][2 * hh + 0] * sc + r.x;
            ov.y = o[nt][2 * hh + 1] * sc + r.y;
            *(float2*)(dst + d) = ov;
            if (f >= 1) {
                uint32_t p = pack_h2(ov.x, ov.y);
                xd[d >> 1] = *(__half2*)&p;
            }
        }
    }
}

// ---------------------------------------------------------------------------
extern "C" void kernel_launch(void* const* d_in, const int* in_sizes, int n_in,
                              void* d_out, int out_size)
{
    const float* x  = (const float*)d_in[0];
    const float* Wq = (const float*)d_in[1];
    const float* Wk = (const float*)d_in[2];
    const float* Wv = (const float*)d_in[3];
    const float* bq = (const float*)d_in[4];
    const float* bk = (const float*)d_in[5];
    const float* bv = (const float*)d_in[6];
    float* out = (float*)d_out;

    cudaFuncSetAttribute(fused_kernel, cudaFuncAttributeMaxDynamicSharedMemorySize,
                         FUSED_SMEM);

    wtrans_kernel<<<(NH * JC * (CH / 2) + 255) / 256, 256>>>(Wq, Wk, Wv);
    xprep_kernel<<<(NWIN * 512 * CH / 4 + 255) / 256, 256>>>(x);

    for (int pass = 0; pass <= 4; pass++) {
        fused_kernel<<<NWIN * NH, 512, FUSED_SMEM>>>(out, x, pass, bq, bk, bv);
    }
}